// round 6
// baseline (speedup 1.0000x reference)
#include <cuda_runtime.h>
#include <cstdint>

#define NH      128
#define NCODES  512
#define NCELLS  65536
#define NEDGES  (NCELLS + 1)
#define NCOARSE 4096                   // 16 fine cells per coarse cell
#define CPW     4                      // coarse cells per warp
#define NCWARPS (NCOARSE / CPW)        // 1024 warps
#define XMIN    (-5.75f)
#define XMAX    (5.75f)
#define CW      (11.5f / 65536.0f)
#define INV_CW  (65536.0f / 11.5f)
#define FULLM   0xffffffffu

__device__ __forceinline__ float neg_inf() { return __int_as_float(0xff800000); }
__device__ __forceinline__ float pos_inf() { return __int_as_float(0x7f800000); }

// -------- device scratch (no allocation allowed) --------
__device__ float  g_ksort[NH];          // sorted kink positions (+inf padded)
__device__ int    g_actRank[NH];        // rank for activity test (128 = never)
__device__ int    g_sgn[NH];
__device__ float  g_A[129 * NCODES];    // per-interval intercepts
__device__ float  g_B[129 * NCODES];    // per-interval slopes
__device__ float  g_score[NCODES];      // dec_w . emb[c]
__device__ float  g_decb;
__device__ unsigned char g_kinkNear[NCELLS];  // set-only, deterministic per replay
__device__ float2 g_cellVF[NCELLS];     // {score[idx]+dec_b, idx + (bad?1024:0)}

// -------- kernel 1: block 0 = kinks/ranks/flags, blocks 1..128 = scores --------
__global__ void k_setup(const float* __restrict__ w1, const float* __restrict__ b1,
                        const float* __restrict__ emb, const float* __restrict__ dec_w,
                        const float* __restrict__ dec_b)
{
    if (blockIdx.x == 0) {
        __shared__ float sk[NH];
        int t = threadIdx.x;             // 128 threads
        float w = w1[t], b = b1[t];
        float kv = (w != 0.0f) ? (-b / w) : pos_inf();
        sk[t] = kv;
        __syncthreads();
        int r = 0;
        #pragma unroll 8
        for (int k = 0; k < NH; k++) {
            float o = sk[k];
            r += (o < kv) || (o == kv && k < t);   // unique rank via index tiebreak
        }
        g_ksort[r] = kv;
        g_actRank[t] = (w != 0.0f) ? r : NH;
        g_sgn[t] = (w > 0.0f) ? 1 : ((w < 0.0f) ? -1 : ((b > 0.0f) ? -1 : 1));
        if (t == 0) g_decb = dec_b[0];
        // flag the 3 cells around this kink (set-only; unsorted value suffices)
        if (kv >= XMIN - 2.0f * CW && kv < XMAX + 2.0f * CW) {
            int g = (int)floorf((kv - XMIN) * INV_CW);
            #pragma unroll
            for (int d = -1; d <= 1; d++) {
                int c = g + d;
                if (c >= 0 && c < NCELLS) g_kinkNear[c] = 1;
            }
        }
    } else {
        // score[c] = dec_w . emb[c] ; 128 blocks x 4 warps = 512 warps, one per code
        int code = (blockIdx.x - 1) * 4 + (threadIdx.x >> 5);
        int lane = threadIdx.x & 31;
        const float* er = emb + code * 256;
        float s = 0.0f;
        #pragma unroll
        for (int k = 0; k < 8; k++) {
            int d = lane + (k << 5);
            s = fmaf(dec_w[d], er[d], s);
        }
        #pragma unroll
        for (int off = 16; off >= 1; off >>= 1)
            s += __shfl_down_sync(FULLM, s, off);
        if (lane == 0) g_score[code] = s;
    }
}

// -------- kernel 2: per-interval line coefficients (direct sums) --------
__global__ void k_ab(const float* __restrict__ w1, const float* __restrict__ b1,
                     const float* __restrict__ w2, const float* __restrict__ b2)
{
    __shared__ float sw[NH], sb[NH];
    __shared__ int   sR[NH], sS[NH];
    int t = threadIdx.x;                 // 512 threads = code c
    int i = blockIdx.x;                  // interval 0..128
    if (t < NH) { sw[t] = w1[t]; sb[t] = b1[t]; sR[t] = g_actRank[t]; sS[t] = g_sgn[t]; }
    __syncthreads();
    float A = b2[t], Bv = 0.0f;
    const float* wr = w2 + t * NH;
    for (int j = 0; j < NH; j++) {
        bool act = (sS[j] > 0) ? (sR[j] < i) : (sR[j] >= i);
        if (act) {                       // warp-uniform predicate
            float v = wr[j];
            A  = fmaf(v, sb[j], A);
            Bv = fmaf(v, sw[j], Bv);
        }
    }
    g_A[i * NCODES + t] = A;
    g_B[i * NCODES + t] = Bv;
}

__device__ __forceinline__ int find_interval(const float* sk, float x) {
    int lo = 0, hi = NH;
    #pragma unroll
    for (int it = 0; it < 8; it++) {
        if (lo < hi) {
            int mid = (lo + hi) >> 1;
            if (sk[mid] <= x) lo = mid + 1; else hi = mid;
        }
    }
    return lo;   // number of kinks <= x, in [0,128]
}

// exact 512-line argmax from GLOBAL tables (rare fallback path in k_main)
__device__ __forceinline__ void scan512(const float* __restrict__ Ar,
                                        const float* __restrict__ Br,
                                        float xv, int lane, int& out_idx)
{
    float best = neg_inf(); int bi = 0;
    #pragma unroll
    for (int k = 0; k < 16; k++) {
        int c = lane + (k << 5);
        float v = fmaf(Br[c], xv, Ar[c]);
        if (v > best) { best = v; bi = c; }        // ascending c -> first-max per lane
    }
    #pragma unroll
    for (int off = 16; off >= 1; off >>= 1) {
        float ov = __shfl_down_sync(FULLM, best, off);
        int   oi = __shfl_down_sync(FULLM, bi,  off);
        if (ov > best || (ov == best && oi < bi)) { best = ov; bi = oi; }
    }
    out_idx = __shfl_sync(FULLM, bi, 0);           // jnp.argmax first-index semantics
}

// -------- kernel 3: coarse-to-fine classification, one warp per 4 coarse cells --------
// Lemma: two linear functions — if L1 >= L2 at both endpoints of a kink-free span,
// L1 >= L2 throughout. So equal endpoint argmax + no kink => constant argmax in cell.
__global__ void k_classify()
{
    __shared__ float sk[NH];
    int tid = threadIdx.x;
    if (tid < NH) sk[tid] = g_ksort[tid];
    __syncthreads();
    int wg = blockIdx.x * (blockDim.x >> 5) + (tid >> 5);
    if (wg >= NCWARPS) return;
    int lane = tid & 31;
    int c0 = wg * CPW;

    float a[16], b[16];
    int iload = -1;
    float xl0 = XMIN + (float)(c0 * 16) * CW;
    int iv = find_interval(sk, xl0);

    auto evalArg = [&](float x) -> int {
        while (iv < NH && sk[iv] <= x) iv++;       // warp-uniform
        if (iv != iload) {
            const float* Ar = g_A + iv * NCODES + lane;
            const float* Br = g_B + iv * NCODES + lane;
            #pragma unroll
            for (int k = 0; k < 16; k++) { a[k] = Ar[k << 5]; b[k] = Br[k << 5]; }
            iload = iv;
        }
        float best = neg_inf(); int bi = 0;
        #pragma unroll
        for (int k = 0; k < 16; k++) {
            float v = fmaf(b[k], x, a[k]);
            if (v > best) { best = v; bi = lane + (k << 5); }
        }
        #pragma unroll
        for (int off = 16; off >= 1; off >>= 1) {
            float ov = __shfl_down_sync(FULLM, best, off);
            int   oi = __shfl_down_sync(FULLM, bi,  off);
            if (ov > best || (ov == best && oi < bi)) { best = ov; bi = oi; }
        }
        return __shfl_sync(FULLM, bi, 0);
    };

    float db = g_decb;
    int argL = evalArg(xl0);
    for (int cc = 0; cc < CPW; cc++) {
        int c = c0 + cc;
        float xr = XMIN + (float)((c + 1) * 16) * CW;
        int ivL = iv;
        int argR = evalArg(xr);
        int ivR = iv;
        bool dirty = (argR != argL) || (ivR != ivL);
        if (!dirty) {
            // constant argmax across all 16 fine cells
            if (lane < 16) {
                int cell = c * 16 + lane;
                float val = g_score[argL] + db;
                int enc = argL + (g_kinkNear[cell] ? 1024 : 0);
                g_cellVF[cell] = make_float2(val, (float)enc);
            }
        } else {
            // evaluate all interior fine edges of this coarse cell
            int ap = argL;
            iv = ivL;                                // rewind interval to cell's left
            for (int t = 0; t < 16; t++) {
                int an;
                if (t == 15) { an = argR; iv = ivR; }
                else {
                    float xf = XMIN + (float)(c * 16 + t + 1) * CW;
                    an = evalArg(xf);
                }
                int cell = c * 16 + t;
                bool bad = (ap != an) || g_kinkNear[cell];
                if (lane == 0) {
                    float val = g_score[ap] + db;
                    g_cellVF[cell] = make_float2(val, (float)(ap + (bad ? 1024 : 0)));
                }
                ap = an;
            }
        }
        argL = argR;
    }
}

// -------- kernel 4: per-element single-load lookup + rare warp fallback --------
__global__ void k_main(const float* __restrict__ x_in, float* __restrict__ out,
                       int n, int write_idx)
{
    __shared__ float sk[NH];
    if (threadIdx.x < NH) sk[threadIdx.x] = g_ksort[threadIdx.x];
    __syncthreads();
    int t = blockIdx.x * blockDim.x + threadIdx.x;
    int base = t * 4;
    bool active = base < n;
    bool full = active && (base + 3 < n);
    float xs[4] = {0.f, 0.f, 0.f, 0.f};
    if (full) {
        float4 xv = *(const float4*)(x_in + base);
        xs[0] = xv.x; xs[1] = xv.y; xs[2] = xv.z; xs[3] = xv.w;
    } else if (active) {
        for (int u = 0; u < 4 && base + u < n; u++) xs[u] = x_in[base + u];
    }
    float val[4]; int idx[4]; bool need[4];
    #pragma unroll
    for (int u = 0; u < 4; u++) {
        float x = xs[u];
        idx[u] = 0; val[u] = 0.0f;
        need[u] = active && (base + u < n);
        if (need[u] && x >= XMIN && x < XMAX) {
            int g = (int)((x - XMIN) * INV_CW);
            if (g >= NCELLS) g = NCELLS - 1;
            float2 vf = g_cellVF[g];                 // single 8B random load
            int enc = (int)vf.y;
            idx[u] = enc & 511;
            val[u] = vf.x;
            need[u] = enc >= 1024;
        }
    }
    int lane = threadIdx.x & 31;
    #pragma unroll
    for (int u = 0; u < 4; u++) {
        unsigned m = __ballot_sync(FULLM, need[u]);
        while (m) {                      // whole warp cooperates per fallback element
            int src = __ffs(m) - 1; m &= m - 1;
            float xb = __shfl_sync(FULLM, xs[u], src);
            int ib = find_interval(sk, xb);          // warp-uniform
            int bi;
            scan512(g_A + ib * NCODES, g_B + ib * NCODES, xb, lane, bi);
            if (lane == src) {
                idx[u] = bi;
                val[u] = g_score[bi] + g_decb;
            }
        }
    }
    if (!active) return;
    if (full) {
        *(float4*)(out + base) = make_float4(val[0], val[1], val[2], val[3]);
        if (write_idx)
            *(float4*)(out + n + base) =
                make_float4((float)idx[0], (float)idx[1], (float)idx[2], (float)idx[3]);
    } else {
        for (int u = 0; u < 4 && base + u < n; u++) {
            out[base + u] = val[u];
            if (write_idx) out[n + base + u] = (float)idx[u];
        }
    }
}

extern "C" void kernel_launch(void* const* d_in, const int* in_sizes, int n_in,
                              void* d_out, int out_size)
{
    const float* x     = (const float*)d_in[0];
    const float* w1    = (const float*)d_in[1];
    const float* b1    = (const float*)d_in[2];
    const float* w2    = (const float*)d_in[3];
    const float* b2    = (const float*)d_in[4];
    const float* emb   = (const float*)d_in[5];
    const float* dec_w = (const float*)d_in[6];
    const float* dec_b = (const float*)d_in[7];
    int n = in_sizes[0];
    float* out = (float*)d_out;

    k_setup<<<129, 128>>>(w1, b1, emb, dec_w, dec_b);
    k_ab<<<129, 512>>>(w1, b1, w2, b2);
    k_classify<<<NCWARPS / 8, 256>>>();
    int write_idx = (out_size >= 2 * n) ? 1 : 0;
    int nthreads = (n + 3) / 4;
    k_main<<<(nthreads + 255) / 256, 256>>>(x, out, n, write_idx);
}

// round 8
// speedup vs baseline: 1.3379x; 1.3379x over previous
#include <cuda_runtime.h>
#include <cstdint>

#define NH      128
#define NCODES  512
#define NCELLS  65536
#define NCOARSE 4096                   // 16 fine cells per coarse cell
#define CPW     2                      // coarse cells per warp
#define NCWARPS (NCOARSE / CPW)        // 2048 warps
#define XMIN    (-5.75f)
#define XMAX    (5.75f)
#define CW      (11.5f / 65536.0f)
#define INV_CW  (65536.0f / 11.5f)
#define FULLM   0xffffffffu

__device__ __forceinline__ float neg_inf() { return __int_as_float(0xff800000); }
__device__ __forceinline__ float pos_inf() { return __int_as_float(0x7f800000); }

// -------- device scratch (no allocation allowed) --------
__device__ float  g_ksort[NH];          // sorted kink positions (+inf padded)
__device__ int    g_actRank[NH];        // rank for activity test (128 = never)
__device__ int    g_sgn[NH];
__device__ float  g_A[129 * NCODES];    // per-interval intercepts
__device__ float  g_B[129 * NCODES];    // per-interval slopes
__device__ float  g_score[NCODES];      // dec_w . emb[c]
__device__ float  g_decb;
__device__ unsigned char g_kinkNear[NCELLS];  // set-only, deterministic per replay
__device__ float2 g_cellVF[NCELLS];     // {score[idx]+dec_b, idx + (bad?1024:0)}

// -------- kernel 1: block 0 = kinks/ranks/flags, blocks 1..128 = scores --------
__global__ void k_setup(const float* __restrict__ w1, const float* __restrict__ b1,
                        const float* __restrict__ emb, const float* __restrict__ dec_w,
                        const float* __restrict__ dec_b)
{
    if (blockIdx.x == 0) {
        __shared__ float sk[NH];
        int t = threadIdx.x;             // 128 threads
        float w = w1[t], b = b1[t];
        float kv = (w != 0.0f) ? (-b / w) : pos_inf();
        sk[t] = kv;
        __syncthreads();
        int r = 0;
        #pragma unroll 8
        for (int k = 0; k < NH; k++) {
            float o = sk[k];
            r += (o < kv) || (o == kv && k < t);   // unique rank via index tiebreak
        }
        g_ksort[r] = kv;
        g_actRank[t] = (w != 0.0f) ? r : NH;
        g_sgn[t] = (w > 0.0f) ? 1 : ((w < 0.0f) ? -1 : ((b > 0.0f) ? -1 : 1));
        if (t == 0) g_decb = dec_b[0];
        // flag the 3 cells around this kink (set-only; unsorted value suffices)
        if (kv >= XMIN - 2.0f * CW && kv < XMAX + 2.0f * CW) {
            int g = (int)floorf((kv - XMIN) * INV_CW);
            #pragma unroll
            for (int d = -1; d <= 1; d++) {
                int c = g + d;
                if (c >= 0 && c < NCELLS) g_kinkNear[c] = 1;
            }
        }
    } else {
        // score[c] = dec_w . emb[c] ; 128 blocks x 4 warps = 512 warps, one per code
        int code = (blockIdx.x - 1) * 4 + (threadIdx.x >> 5);
        int lane = threadIdx.x & 31;
        const float* er = emb + code * 256;
        float s = 0.0f;
        #pragma unroll
        for (int k = 0; k < 8; k++) {
            int d = lane + (k << 5);
            s = fmaf(dec_w[d], er[d], s);
        }
        #pragma unroll
        for (int off = 16; off >= 1; off >>= 1)
            s += __shfl_down_sync(FULLM, s, off);
        if (lane == 0) g_score[code] = s;
    }
}

// -------- kernel 2: per-interval line coefficients (direct sums) --------
__global__ void k_ab(const float* __restrict__ w1, const float* __restrict__ b1,
                     const float* __restrict__ w2, const float* __restrict__ b2)
{
    __shared__ float sw[NH], sb[NH];
    __shared__ int   sR[NH], sS[NH];
    int t = threadIdx.x;                 // 512 threads = code c
    int i = blockIdx.x;                  // interval 0..128
    if (t < NH) { sw[t] = w1[t]; sb[t] = b1[t]; sR[t] = g_actRank[t]; sS[t] = g_sgn[t]; }
    __syncthreads();
    float A = b2[t], Bv = 0.0f;
    const float* wr = w2 + t * NH;
    for (int j = 0; j < NH; j++) {
        bool act = (sS[j] > 0) ? (sR[j] < i) : (sR[j] >= i);
        if (act) {                       // warp-uniform predicate
            float v = wr[j];
            A  = fmaf(v, sb[j], A);
            Bv = fmaf(v, sw[j], Bv);
        }
    }
    g_A[i * NCODES + t] = A;
    g_B[i * NCODES + t] = Bv;
}

__device__ __forceinline__ int find_interval(const float* sk, float x) {
    int lo = 0, hi = NH;
    #pragma unroll
    for (int it = 0; it < 8; it++) {
        if (lo < hi) {
            int mid = (lo + hi) >> 1;
            if (sk[mid] <= x) lo = mid + 1; else hi = mid;
        }
    }
    return lo;   // number of kinks <= x, in [0,128]
}

// exact 512-line argmax from GLOBAL tables (rare fallback path in k_main)
__device__ __forceinline__ void scan512(const float* __restrict__ Ar,
                                        const float* __restrict__ Br,
                                        float xv, int lane, int& out_idx)
{
    float best = neg_inf(); int bi = 0;
    #pragma unroll
    for (int k = 0; k < 16; k++) {
        int c = lane + (k << 5);
        float v = fmaf(Br[c], xv, Ar[c]);
        if (v > best) { best = v; bi = c; }        // ascending c -> first-max per lane
    }
    #pragma unroll
    for (int off = 16; off >= 1; off >>= 1) {
        float ov = __shfl_down_sync(FULLM, best, off);
        int   oi = __shfl_down_sync(FULLM, bi,  off);
        if (ov > best || (ov == best && oi < bi)) { best = ov; bi = oi; }
    }
    out_idx = __shfl_sync(FULLM, bi, 0);           // jnp.argmax first-index semantics
}

// -------- kernel 3: coarse-to-fine classification with bisection --------
// Pairwise-dominance lemma: within a kink-free span, each line's dominance
// region is an interval, so equal endpoint argmax (+ same kink-interval)
// implies constant argmax across the span. Dirty spans are bisected.
__global__ void k_classify()
{
    __shared__ float sk[NH];
    int tid = threadIdx.x;
    if (tid < NH) sk[tid] = g_ksort[tid];
    __syncthreads();
    int wg = blockIdx.x * (blockDim.x >> 5) + (tid >> 5);
    if (wg >= NCWARPS) return;
    int lane = tid & 31;
    int c0 = wg * CPW;

    float a[16], b[16];
    int iload = -1;
    int ivCur = 0;

    auto evalEdge = [&](int e) -> int {          // warp-cooperative 512-line argmax
        float x = XMIN + (float)e * CW;
        int iv = find_interval(sk, x);           // warp-uniform
        if (iv != iload) {
            const float* Ar = g_A + iv * NCODES + lane;
            const float* Br = g_B + iv * NCODES + lane;
            #pragma unroll
            for (int k = 0; k < 16; k++) { a[k] = Ar[k << 5]; b[k] = Br[k << 5]; }
            iload = iv;
        }
        ivCur = iv;
        float best = neg_inf(); int bi = 0;
        #pragma unroll
        for (int k = 0; k < 16; k++) {
            float v = fmaf(b[k], x, a[k]);
            if (v > best) { best = v; bi = lane + (k << 5); }
        }
        #pragma unroll
        for (int off = 16; off >= 1; off >>= 1) {
            float ov = __shfl_down_sync(FULLM, best, off);
            int   oi = __shfl_down_sync(FULLM, bi,  off);
            if (ov > best || (ov == best && oi < bi)) { best = ov; bi = oi; }
        }
        return __shfl_sync(FULLM, bi, 0);
    };

    float db = g_decb;
    auto fill = [&](int loE, int hiE, int arg) { // lanes cover <=16 cells in parallel
        int cell = loE + lane;
        if (cell < hiE) {
            float val = g_score[arg] + db;
            int enc = arg + (g_kinkNear[cell] ? 1024 : 0);
            g_cellVF[cell] = make_float2(val, (float)enc);
        }
    };

    int argL = evalEdge(c0 * 16);
    int ivL = ivCur;
    for (int cc = 0; cc < CPW; cc++) {
        int loE = (c0 + cc) * 16, hiE = loE + 16;
        int argR = evalEdge(hiE);
        int ivR = ivCur;
        if (argL == argR && ivL == ivR) {
            fill(loE, hiE, argL);
        } else {
            // warp-uniform bisection stack (depth <= 5)
            int sLo[8], sHi[8], sAL[8], sAH[8], sIL[8], sIH[8];
            int sp = 0;
            sLo[0] = loE; sHi[0] = hiE; sAL[0] = argL; sAH[0] = argR;
            sIL[0] = ivL; sIH[0] = ivR; sp = 1;
            while (sp) {
                sp--;
                int lo = sLo[sp], hi = sHi[sp];
                int aL = sAL[sp], aH = sAH[sp], iL = sIL[sp], iH = sIH[sp];
                if (aL == aH && iL == iH) { fill(lo, hi, aL); continue; }
                if (hi - lo == 1) {                  // boundary/kink inside: bad cell
                    if (lane == 0) {
                        float val = g_score[aL] + db;
                        g_cellVF[lo] = make_float2(val, (float)(aL + 1024));
                    }
                    continue;
                }
                int mid = (lo + hi) >> 1;
                int aM = evalEdge(mid);
                int iM = ivCur;
                sLo[sp] = lo;  sHi[sp] = mid; sAL[sp] = aL; sAH[sp] = aM;
                sIL[sp] = iL;  sIH[sp] = iM;  sp++;
                sLo[sp] = mid; sHi[sp] = hi;  sAL[sp] = aM; sAH[sp] = aH;
                sIL[sp] = iM;  sIH[sp] = iH;  sp++;
            }
        }
        argL = argR; ivL = ivR;
    }
}

// -------- kernel 4: one element per thread, single-load lookup + rare fallback --------
__global__ void k_main(const float* __restrict__ x_in, float* __restrict__ out,
                       int n, int write_idx)
{
    __shared__ float sk[NH];
    if (threadIdx.x < NH) sk[threadIdx.x] = g_ksort[threadIdx.x];
    __syncthreads();
    int b = blockIdx.x * blockDim.x + threadIdx.x;
    bool active = b < n;
    float x = 0.0f;
    if (active) x = x_in[b];
    int idx = 0; float val = 0.0f;
    bool need = active;
    if (need && x >= XMIN && x < XMAX) {
        int g = (int)((x - XMIN) * INV_CW);
        if (g >= NCELLS) g = NCELLS - 1;
        float2 vf = g_cellVF[g];                  // single 8B random L2 load
        int enc = (int)vf.y;
        idx = enc & 511;
        val = vf.x;
        need = enc >= 1024;
    }
    int lane = threadIdx.x & 31;
    unsigned m = __ballot_sync(FULLM, need);
    while (m) {                                   // whole warp per fallback element
        int src = __ffs(m) - 1; m &= m - 1;
        float xb = __shfl_sync(FULLM, x, src);
        int ib = find_interval(sk, xb);           // warp-uniform
        int bi;
        scan512(g_A + ib * NCODES, g_B + ib * NCODES, xb, lane, bi);
        if (lane == src) {
            idx = bi;
            val = g_score[bi] + g_decb;
        }
    }
    if (!active) return;
    out[b] = val;
    if (write_idx) out[n + b] = (float)idx;
}

extern "C" void kernel_launch(void* const* d_in, const int* in_sizes, int n_in,
                              void* d_out, int out_size)
{
    const float* x     = (const float*)d_in[0];
    const float* w1    = (const float*)d_in[1];
    const float* b1    = (const float*)d_in[2];
    const float* w2    = (const float*)d_in[3];
    const float* b2    = (const float*)d_in[4];
    const float* emb   = (const float*)d_in[5];
    const float* dec_w = (const float*)d_in[6];
    const float* dec_b = (const float*)d_in[7];
    int n = in_sizes[0];
    float* out = (float*)d_out;

    k_setup<<<129, 128>>>(w1, b1, emb, dec_w, dec_b);
    k_ab<<<129, 512>>>(w1, b1, w2, b2);
    k_classify<<<NCWARPS / 8, 256>>>();
    int write_idx = (out_size >= 2 * n) ? 1 : 0;
    k_main<<<(n + 255) / 256, 256>>>(x, out, n, write_idx);
}

// round 10
// speedup vs baseline: 1.3818x; 1.0328x over previous
#include <cuda_runtime.h>
#include <cstdint>

#define NH      128
#define NCODES  512
#define NCELLS  65536
#define NCOARSE 4096                   // 16 fine cells per coarse cell
#define XMIN    (-5.75f)
#define XMAX    (5.75f)
#define CW      (11.5f / 65536.0f)
#define INV_CW  (65536.0f / 11.5f)
#define FULLM   0xffffffffu

__device__ __forceinline__ float neg_inf() { return __int_as_float(0xff800000); }
__device__ __forceinline__ float pos_inf() { return __int_as_float(0x7f800000); }

// -------- device scratch (no allocation allowed) --------
__device__ float    g_ksort[NH];        // sorted kink positions (+inf padded)
__device__ float    g_A[129 * NCODES];  // per-interval intercepts
__device__ float    g_B[129 * NCODES];  // per-interval slopes
__device__ float    g_score[NCODES];    // dec_w . emb[c]
__device__ float    g_decb;
__device__ unsigned char g_kinkNear[NCELLS];   // set-only, deterministic per replay
__device__ unsigned short g_cellEnc[NCELLS];   // idx | (bad ? 0x8000 : 0)

// ======== kernel 1 (fused prep): blocks 0-128 AB, block 129 setup, 130-161 scores ====
__global__ void k_prep(const float* __restrict__ w1, const float* __restrict__ b1,
                       const float* __restrict__ w2, const float* __restrict__ b2,
                       const float* __restrict__ emb, const float* __restrict__ dec_w,
                       const float* __restrict__ dec_b)
{
    int blk = blockIdx.x;
    int t = threadIdx.x;                 // 512 threads
    if (blk < 129) {
        // ---- per-interval line coefficients, ranks recomputed locally ----
        __shared__ float sw[NH], sb[NH], skv[NH];
        __shared__ int   sR[NH], sS[NH];
        if (t < NH) {
            float w = w1[t], b = b1[t];
            sw[t] = w; sb[t] = b;
            skv[t] = (w != 0.0f) ? (-b / w) : pos_inf();
        }
        __syncthreads();
        if (t < NH) {
            float kv = skv[t];
            int r = 0;
            #pragma unroll 8
            for (int k = 0; k < NH; k++) {
                float o = skv[k];
                r += (o < kv) || (o == kv && k < t);   // unique rank, index tiebreak
            }
            float w = sw[t], b = sb[t];
            sR[t] = (w != 0.0f) ? r : NH;
            sS[t] = (w > 0.0f) ? 1 : ((w < 0.0f) ? -1 : ((b > 0.0f) ? -1 : 1));
        }
        __syncthreads();
        int i = blk;                     // interval 0..128
        float A = b2[t], Bv = 0.0f;
        const float* wr = w2 + t * NH;
        for (int j = 0; j < NH; j++) {
            bool act = (sS[j] > 0) ? (sR[j] < i) : (sR[j] >= i);
            if (act) {                   // warp-uniform predicate
                float v = wr[j];
                A  = fmaf(v, sb[j], A);
                Bv = fmaf(v, sw[j], Bv);
            }
        }
        g_A[i * NCODES + t] = A;
        g_B[i * NCODES + t] = Bv;
    } else if (blk == 129) {
        // ---- sorted kinks, kink-adjacent flags, decoder bias ----
        __shared__ float skv[NH];
        if (t < NH) {
            float w = w1[t], b = b1[t];
            skv[t] = (w != 0.0f) ? (-b / w) : pos_inf();
        }
        __syncthreads();
        if (t < NH) {
            float kv = skv[t];
            int r = 0;
            #pragma unroll 8
            for (int k = 0; k < NH; k++) {
                float o = skv[k];
                r += (o < kv) || (o == kv && k < t);
            }
            g_ksort[r] = kv;
            if (kv >= XMIN - 2.0f * CW && kv < XMAX + 2.0f * CW) {
                int g = (int)floorf((kv - XMIN) * INV_CW);
                #pragma unroll
                for (int d = -1; d <= 1; d++) {
                    int c = g + d;
                    if (c >= 0 && c < NCELLS) g_kinkNear[c] = 1;
                }
            }
        }
        if (t == 0) g_decb = dec_b[0];
    } else {
        // ---- score[c] = dec_w . emb[c]; 32 blocks x 16 warps = 512 warps ----
        int code = (blk - 130) * 16 + (t >> 5);
        int lane = t & 31;
        const float* er = emb + code * 256;
        float s = 0.0f;
        #pragma unroll
        for (int k = 0; k < 8; k++) {
            int d = lane + (k << 5);
            s = fmaf(dec_w[d], er[d], s);
        }
        #pragma unroll
        for (int off = 16; off >= 1; off >>= 1)
            s += __shfl_down_sync(FULLM, s, off);
        if (lane == 0) g_score[code] = s;
    }
}

__device__ __forceinline__ int find_interval(const float* sk, float x) {
    int lo = 0, hi = NH;
    #pragma unroll
    for (int it = 0; it < 8; it++) {
        if (lo < hi) {
            int mid = (lo + hi) >> 1;
            if (sk[mid] <= x) lo = mid + 1; else hi = mid;
        }
    }
    return lo;   // number of kinks <= x, in [0,128]
}

// exact 512-line argmax from GLOBAL tables (rare fallback path in k_main)
__device__ __forceinline__ void scan512(const float* __restrict__ Ar,
                                        const float* __restrict__ Br,
                                        float xv, int lane, int& out_idx)
{
    float best = neg_inf(); int bi = 0;
    #pragma unroll
    for (int k = 0; k < 16; k++) {
        int c = lane + (k << 5);
        float v = fmaf(Br[c], xv, Ar[c]);
        if (v > best) { best = v; bi = c; }        // ascending c -> first-max per lane
    }
    #pragma unroll
    for (int off = 16; off >= 1; off >>= 1) {
        float ov = __shfl_down_sync(FULLM, best, off);
        int   oi = __shfl_down_sync(FULLM, bi,  off);
        if (ov > best || (ov == best && oi < bi)) { best = ov; bi = oi; }
    }
    out_idx = __shfl_sync(FULLM, bi, 0);           // jnp.argmax first-index semantics
}

// ======== kernel 2: coarse-to-fine classification with bisection, 1 coarse/warp ====
// Pairwise-dominance: within a kink-free span each line's dominance region is an
// interval -> equal endpoint argmax (+ same kink-interval) => constant throughout.
__global__ void k_classify()
{
    __shared__ float sk[NH];
    int tid = threadIdx.x;
    if (tid < NH) sk[tid] = g_ksort[tid];
    __syncthreads();
    int wg = blockIdx.x * (blockDim.x >> 5) + (tid >> 5);
    if (wg >= NCOARSE) return;
    int lane = tid & 31;

    float a[16], b[16];
    int iload = -1;
    int ivCur = 0;

    auto evalEdge = [&](int e) -> int {          // warp-cooperative 512-line argmax
        float x = XMIN + (float)e * CW;
        int iv = find_interval(sk, x);           // warp-uniform
        if (iv != iload) {
            const float* Ar = g_A + iv * NCODES + lane;
            const float* Br = g_B + iv * NCODES + lane;
            #pragma unroll
            for (int k = 0; k < 16; k++) { a[k] = Ar[k << 5]; b[k] = Br[k << 5]; }
            iload = iv;
        }
        ivCur = iv;
        float best = neg_inf(); int bi = 0;
        #pragma unroll
        for (int k = 0; k < 16; k++) {
            float v = fmaf(b[k], x, a[k]);
            if (v > best) { best = v; bi = lane + (k << 5); }
        }
        #pragma unroll
        for (int off = 16; off >= 1; off >>= 1) {
            float ov = __shfl_down_sync(FULLM, best, off);
            int   oi = __shfl_down_sync(FULLM, bi,  off);
            if (ov > best || (ov == best && oi < bi)) { best = ov; bi = oi; }
        }
        return __shfl_sync(FULLM, bi, 0);
    };

    auto fill = [&](int loE, int hiE, int arg) { // lanes cover <=16 cells in parallel
        int cell = loE + lane;
        if (cell < hiE)
            g_cellEnc[cell] =
                (unsigned short)(arg | (g_kinkNear[cell] ? 0x8000 : 0));
    };

    int loE = wg * 16, hiE = loE + 16;
    int argL = evalEdge(loE); int ivL = ivCur;
    int argR = evalEdge(hiE); int ivR = ivCur;
    if (argL == argR && ivL == ivR) {
        fill(loE, hiE, argL);
        return;
    }
    // warp-uniform bisection stack (depth <= 4)
    int sLo[8], sHi[8], sAL[8], sAH[8], sIL[8], sIH[8];
    sLo[0] = loE; sHi[0] = hiE; sAL[0] = argL; sAH[0] = argR;
    sIL[0] = ivL; sIH[0] = ivR;
    int sp = 1;
    while (sp) {
        sp--;
        int lo = sLo[sp], hi = sHi[sp];
        int aL = sAL[sp], aH = sAH[sp], iL = sIL[sp], iH = sIH[sp];
        if (aL == aH && iL == iH) { fill(lo, hi, aL); continue; }
        if (hi - lo == 1) {                      // boundary/kink inside: bad cell
            if (lane == 0)
                g_cellEnc[lo] = (unsigned short)(aL | 0x8000);
            continue;
        }
        int mid = (lo + hi) >> 1;
        int aM = evalEdge(mid);
        int iM = ivCur;
        sLo[sp] = lo;  sHi[sp] = mid; sAL[sp] = aL; sAH[sp] = aM;
        sIL[sp] = iL;  sIH[sp] = iM;  sp++;
        sLo[sp] = mid; sHi[sp] = hi;  sAL[sp] = aM; sAH[sp] = aH;
        sIL[sp] = iM;  sIH[sp] = iH;  sp++;
    }
}

// ======== kernel 3: 2 elems/thread, u16 gather + smem score LUT + rare fallback ====
__global__ void k_main(const float* __restrict__ x_in, float* __restrict__ out,
                       int n, int write_idx)
{
    __shared__ float s_sc[NCODES];
    __shared__ float s_sk[NH];
    int tid = threadIdx.x;
    s_sc[tid] = g_score[tid];
    s_sc[tid + 256] = g_score[tid + 256];
    if (tid < NH) s_sk[tid] = g_ksort[tid];
    __syncthreads();
    float db = g_decb;

    int base = (blockIdx.x * blockDim.x + tid) * 2;
    bool a0 = base < n, a1 = base + 1 < n;
    float x0 = 0.0f, x1 = 0.0f;
    if (a1) { float2 xv = *(const float2*)(x_in + base); x0 = xv.x; x1 = xv.y; }
    else if (a0) x0 = x_in[base];

    int idx0 = 0, idx1 = 0;
    bool need0 = a0, need1 = a1;
    unsigned enc0 = 0, enc1 = 0;
    if (a0 && x0 >= XMIN && x0 < XMAX) {
        int g = (int)((x0 - XMIN) * INV_CW);
        if (g >= NCELLS) g = NCELLS - 1;
        enc0 = g_cellEnc[g];
        need0 = (enc0 & 0x8000u) != 0;
    }
    if (a1 && x1 >= XMIN && x1 < XMAX) {
        int g = (int)((x1 - XMIN) * INV_CW);
        if (g >= NCELLS) g = NCELLS - 1;
        enc1 = g_cellEnc[g];
        need1 = (enc1 & 0x8000u) != 0;
    }
    idx0 = enc0 & 511;
    idx1 = enc1 & 511;

    int lane = tid & 31;
    unsigned m = __ballot_sync(FULLM, need0);
    while (m) {
        int src = __ffs(m) - 1; m &= m - 1;
        float xb = __shfl_sync(FULLM, x0, src);
        int ib = find_interval(s_sk, xb);        // warp-uniform
        int bi;
        scan512(g_A + ib * NCODES, g_B + ib * NCODES, xb, lane, bi);
        if (lane == src) idx0 = bi;
    }
    m = __ballot_sync(FULLM, need1);
    while (m) {
        int src = __ffs(m) - 1; m &= m - 1;
        float xb = __shfl_sync(FULLM, x1, src);
        int ib = find_interval(s_sk, xb);
        int bi;
        scan512(g_A + ib * NCODES, g_B + ib * NCODES, xb, lane, bi);
        if (lane == src) idx1 = bi;
    }

    if (a1) {
        *(float2*)(out + base) = make_float2(s_sc[idx0] + db, s_sc[idx1] + db);
        if (write_idx)
            *(float2*)(out + n + base) = make_float2((float)idx0, (float)idx1);
    } else if (a0) {
        out[base] = s_sc[idx0] + db;
        if (write_idx) out[n + base] = (float)idx0;
    }
}

extern "C" void kernel_launch(void* const* d_in, const int* in_sizes, int n_in,
                              void* d_out, int out_size)
{
    const float* x     = (const float*)d_in[0];
    const float* w1    = (const float*)d_in[1];
    const float* b1    = (const float*)d_in[2];
    const float* w2    = (const float*)d_in[3];
    const float* b2    = (const float*)d_in[4];
    const float* emb   = (const float*)d_in[5];
    const float* dec_w = (const float*)d_in[6];
    const float* dec_b = (const float*)d_in[7];
    int n = in_sizes[0];
    float* out = (float*)d_out;

    k_prep<<<162, 512>>>(w1, b1, w2, b2, emb, dec_w, dec_b);
    k_classify<<<NCOARSE / 8, 256>>>();
    int write_idx = (out_size >= 2 * n) ? 1 : 0;
    int nth = (n + 1) / 2;
    k_main<<<(nth + 255) / 256, 256>>>(x, out, n, write_idx);
}